// round 15
// baseline (speedup 1.0000x reference)
#include <cuda_runtime.h>
#include <cuda_fp16.h>
#include <math.h>
#include <stdint.h>

#define BATCH 8
#define T 512
#define D 512
#define H 8
#define HS 64
#define BT (BATCH*T)     // 4096
#define FF 2048

// ===================== device scratch =====================
__device__ __align__(16) float g_x[BT*D];
__device__ __align__(16) float g_q[BT*D];
__device__ __align__(16) float g_src2[BT*D];
__device__ __align__(16) float g_y[BT*D];
__device__ __align__(16) __half g_rel[BATCH*H*T*T];     // 32MB
__device__ __align__(16) __half g_xh[BT*D], g_xl[BT*D];
__device__ __align__(16) __half g_yh[BT*D];
__device__ __align__(16) __half g_qh[BT*D], g_ql[BT*D];
__device__ __align__(16) __half g_k8h[BT*D], g_k8l[BT*D];
__device__ __align__(16) __half g_vth[BATCH*H*HS*T];
__device__ __align__(16) __half g_att[BT*D];
__device__ __align__(16) __half g_hid[BT*FF];
__device__ __align__(16) __half g_w3h[3*D*D], g_w3l[3*D*D];
__device__ __align__(16) __half g_pwh[D*D];
__device__ __align__(16) __half g_f1h[FF*D];
__device__ __align__(16) __half g_f2h[D*FF];

__device__ __forceinline__ void split2h(float v, __half& h, __half& l) {
    h = __float2half_rn(v);
    l = __float2half_rn(v - __half2float(h));
}

// ===================== primitives =====================
__device__ __forceinline__ void mma_f16(float* d, const uint32_t* a, const uint32_t* b) {
    asm volatile(
        "mma.sync.aligned.m16n8k16.row.col.f32.f16.f16.f32 "
        "{%0,%1,%2,%3}, {%4,%5,%6,%7}, {%8,%9}, {%0,%1,%2,%3};"
        : "+f"(d[0]), "+f"(d[1]), "+f"(d[2]), "+f"(d[3])
        : "r"(a[0]), "r"(a[1]), "r"(a[2]), "r"(a[3]), "r"(b[0]), "r"(b[1]));
}
__device__ __forceinline__ void ldsm4(uint32_t* r, uint32_t addr) {
    asm volatile("ldmatrix.sync.aligned.m8n8.x4.shared.b16 {%0,%1,%2,%3}, [%4];"
        : "=r"(r[0]), "=r"(r[1]), "=r"(r[2]), "=r"(r[3]) : "r"(addr));
}
__device__ __forceinline__ uint32_t smem_to_u32(const void* p) {
    uint32_t a;
    asm("{ .reg .u64 t; cvta.to.shared.u64 t, %1; cvt.u32.u64 %0, t; }" : "=r"(a) : "l"(p));
    return a;
}
__device__ __forceinline__ void cp16(uint32_t s, const void* g) {
    asm volatile("{.reg .u64 gp; cvta.to.global.u64 gp, %1; cp.async.cg.shared.global [%0], [gp], 16;}"
        :: "r"(s), "l"(g) : "memory");
}
#define CP_COMMIT asm volatile("cp.async.commit_group;" ::: "memory")
#define CP_WAIT1  asm volatile("cp.async.wait_group 1;" ::: "memory")
#define CP_WAIT0  asm volatile("cp.async.wait_group 0;" ::: "memory")

// ===================== mega0: qkv wsplit + rmsnorm(x) =====================
__device__ __forceinline__ void wsplit_qkv_body(
    const float* __restrict__ Wq, const float* __restrict__ Wk, const float* __restrict__ Wv,
    float (*tile)[33], int bx, int by, int bz)
{
    const int mat = bz >> 3, h = bz & 7;
    const int c0 = by * 32, d0 = bx * 32;
    const int tx = threadIdx.x & 31, ty = threadIdx.x >> 5;
    const float* W = (mat == 0) ? Wq : (mat == 1) ? Wk : Wv;
    #pragma unroll
    for (int i = 0; i < 32; i += 8)
        tile[ty + i][tx] = W[((size_t)h * D + d0 + ty + i) * HS + c0 + tx];
    __syncthreads();
    #pragma unroll
    for (int i = 0; i < 32; i += 8) {
        float v = tile[tx][ty + i];
        __half hh, ll; split2h(v, hh, ll);
        size_t o = (size_t)mat * D * D + (size_t)(h * HS + c0 + ty + i) * D + d0 + tx;
        g_w3h[o] = hh; g_w3l[o] = ll;
    }
}

__device__ __forceinline__ void rmsnorm2_body(const float* __restrict__ in,
    const float* __restrict__ w, int row0,
    float* __restrict__ out, __half* __restrict__ outh, __half* __restrict__ outl,
    float* ws)
{
    const int tid = threadIdx.x;
    const int half = tid >> 7;
    const int t7 = tid & 127;
    const int row = row0 + half;
    const float4 v = ((const float4*)(in + (size_t)row * D))[t7];
    float ss = v.x*v.x + v.y*v.y + v.z*v.z + v.w*v.w;
    #pragma unroll
    for (int o = 16; o > 0; o >>= 1) ss += __shfl_xor_sync(0xffffffffu, ss, o);
    if ((tid & 31) == 0) ws[tid >> 5] = ss;
    __syncthreads();
    const float total = ws[half*4+0] + ws[half*4+1] + ws[half*4+2] + ws[half*4+3];
    const float r = rsqrtf(total * (1.0f / (float)D) + 1e-6f);
    const float4 wv = ((const float4*)w)[t7];
    float4 o;
    o.x = v.x * r * wv.x; o.y = v.y * r * wv.y;
    o.z = v.z * r * wv.z; o.w = v.w * r * wv.w;
    ((float4*)(out + (size_t)row * D))[t7] = o;
    __half h0,l0,h1,l1,h2,l2,h3,l3;
    split2h(o.x,h0,l0); split2h(o.y,h1,l1); split2h(o.z,h2,l2); split2h(o.w,h3,l3);
    size_t base = (size_t)row * D + t7 * 4;
    *(__half2*)(outh + base)     = __halves2half2(h0,h1);
    *(__half2*)(outh + base + 2) = __halves2half2(h2,h3);
    if (outl) {
        *(__half2*)(outl + base)     = __halves2half2(l0,l1);
        *(__half2*)(outl + base + 2) = __halves2half2(l2,l3);
    }
}

__global__ __launch_bounds__(256) void mega0(
    const float* __restrict__ Wq, const float* __restrict__ Wk, const float* __restrict__ Wv,
    const float* __restrict__ src, const float* __restrict__ norm_w)
{
    __shared__ float tile[32][33];
    __shared__ float ws[8];
    const int bid = blockIdx.x;
    if (bid < 768) {
        wsplit_qkv_body(Wq, Wk, Wv, tile, bid & 15, (bid >> 4) & 1, bid >> 5);
    } else {
        rmsnorm2_body(src, norm_w, (bid - 768) * 2, g_x, g_xh, g_xl, ws);
    }
}

// ===================== rmsnorm (single, for y) =====================
__global__ __launch_bounds__(128) void rmsnorm_kernel(
    const float* __restrict__ in, const float* __restrict__ w,
    float* __restrict__ out, __half* __restrict__ outh)
{
    int row = blockIdx.x;
    int tid = threadIdx.x;
    const float4 v = ((const float4*)(in + (size_t)row * D))[tid];
    float ss = v.x*v.x + v.y*v.y + v.z*v.z + v.w*v.w;
    #pragma unroll
    for (int o = 16; o > 0; o >>= 1) ss += __shfl_xor_sync(0xffffffffu, ss, o);
    __shared__ float ws[4];
    if ((tid & 31) == 0) ws[tid >> 5] = ss;
    __syncthreads();
    float total = ws[0] + ws[1] + ws[2] + ws[3];
    float r = rsqrtf(total * (1.0f / (float)D) + 1e-6f);
    const float4 wv = ((const float4*)w)[tid];
    float4 o;
    o.x = v.x * r * wv.x; o.y = v.y * r * wv.y;
    o.z = v.z * r * wv.z; o.w = v.w * r * wv.w;
    ((float4*)(out + (size_t)row * D))[tid] = o;
    size_t base = (size_t)row * D + tid * 4;
    *(__half2*)(outh + base)     = __halves2half2(__float2half_rn(o.x), __float2half_rn(o.y));
    *(__half2*)(outh + base + 2) = __halves2half2(__float2half_rn(o.z), __float2half_rn(o.w));
}

// ===================== tile constants =====================
static constexpr int TROW  = 80;
static constexpr int TILEB = 128 * TROW;      // 10240
static constexpr int G1_SMEM = 3 * 2 * TILEB; // 61440
static constexpr int G3_STG  = 4 * TILEB;     // 40960
static constexpr int G3_SMEM = 2 * G3_STG;    // 81920  (2-stage -> 2 CTAs/SM)

// ===================== merged q/k GEMM (3-product, 2-stage, 2 CTAs/SM) =====
__global__ __launch_bounds__(256, 2) void gemm_qk(
    const float* __restrict__ bq, const float* __restrict__ bk)
{
    extern __shared__ char sm[];
    const int z = blockIdx.z;               // 0: q, 1: k8
    const __half* Ah = g_xh;
    const __half* Al = g_xl;
    const __half* Bh = g_w3h + (size_t)z * D * D;
    const __half* Bl = g_w3l + (size_t)z * D * D;
    const float* bias = z ? bk : bq;
    const float osc = z ? 8.f : 1.f;
    const int K = D, N = D;

    const int tid  = threadIdx.x;
    const int wid  = tid >> 5, lane = tid & 31;
    const int warpM = wid & 1, warpN = wid >> 1;
    const int bm = blockIdx.y * 128, bn = blockIdx.x * 128;
    const uint32_t smb = smem_to_u32(sm);

    const int lrow   = tid >> 2;
    const int lchunk = tid & 3;
    const int soff   = lrow * TROW + lchunk * 16;
    const int a_off = (warpM * 64 + (lane & 15)) * TROW + (lane >> 4) * 16;
    const int b_off = (warpN * 32 + ((lane >> 4) << 3) + (lane & 7)) * TROW + ((lane >> 3) & 1) * 16;

    float acc[4][4][4];
    #pragma unroll
    for (int i = 0; i < 4; i++)
        #pragma unroll
        for (int j = 0; j < 4; j++)
            #pragma unroll
            for (int r = 0; r < 4; r++) acc[i][j][r] = 0.f;

    const int nch = K >> 5;
    auto issue = [&](int c, int s) {
        const int k0 = c << 5;
        const uint32_t st = smb + s * G3_STG;
        const __half* pa  = Ah + (size_t)(bm + lrow) * K + k0 + lchunk * 8;
        const __half* pal = Al + (size_t)(bm + lrow) * K + k0 + lchunk * 8;
        const __half* pb  = Bh + (size_t)(bn + lrow) * K + k0 + lchunk * 8;
        const __half* pbl = Bl + (size_t)(bn + lrow) * K + k0 + lchunk * 8;
        cp16(st + soff, pa);            cp16(st + soff + 64*TROW, pa + (size_t)64*K);
        cp16(st + TILEB + soff, pal);   cp16(st + TILEB + soff + 64*TROW, pal + (size_t)64*K);
        cp16(st + 2*TILEB + soff, pb);  cp16(st + 2*TILEB + soff + 64*TROW, pb + (size_t)64*K);
        cp16(st + 3*TILEB + soff, pbl); cp16(st + 3*TILEB + soff + 64*TROW, pbl + (size_t)64*K);
        CP_COMMIT;
    };
    issue(0, 0);
    issue(1, 1);

    for (int c = 0; c < nch; ++c) {
        if (c + 1 < nch) { CP_WAIT1; } else { CP_WAIT0; }
        __syncthreads();
        const uint32_t sb = smb + (c & 1) * G3_STG;
        #pragma unroll
        for (int ks = 0; ks < 2; ++ks) {
            uint32_t ahr[4][4], alr[4][4], bhr[2][4], blr[2][4];
            #pragma unroll
            for (int i = 0; i < 4; ++i) {
                ldsm4(ahr[i], sb + a_off + i * (16 * TROW) + ks * 32);
                ldsm4(alr[i], sb + TILEB + a_off + i * (16 * TROW) + ks * 32);
            }
            #pragma unroll
            for (int j = 0; j < 2; ++j) {
                ldsm4(bhr[j], sb + 2*TILEB + b_off + j * (16 * TROW) + ks * 32);
                ldsm4(blr[j], sb + 3*TILEB + b_off + j * (16 * TROW) + ks * 32);
            }
            #pragma unroll
            for (int i = 0; i < 4; ++i)
                #pragma unroll
                for (int j = 0; j < 4; ++j) {
                    uint32_t bfh[2] = { bhr[j >> 1][(j & 1) * 2], bhr[j >> 1][(j & 1) * 2 + 1] };
                    uint32_t bfl[2] = { blr[j >> 1][(j & 1) * 2], blr[j >> 1][(j & 1) * 2 + 1] };
                    mma_f16(acc[i][j], ahr[i], bfh);
                    mma_f16(acc[i][j], ahr[i], bfl);
                    mma_f16(acc[i][j], alr[i], bfh);
                }
        }
        __syncthreads();
        if (c + 2 < nch) issue(c + 2, c & 1);
    }

    #pragma unroll
    for (int i = 0; i < 4; ++i) {
        const int m0 = bm + warpM * 64 + i * 16 + (lane >> 2);
        #pragma unroll
        for (int j = 0; j < 4; ++j) {
            const int n = bn + warpN * 32 + j * 8 + (lane & 3) * 2;
            const float b0 = bias[n], b1 = bias[n + 1];
            #pragma unroll
            for (int rr = 0; rr < 2; ++rr) {
                const int m = m0 + rr * 8;
                float v0 = (acc[i][j][rr*2+0] + b0) * osc;
                float v1 = (acc[i][j][rr*2+1] + b1) * osc;
                __half h0,l0,h1,l1;
                split2h(v0,h0,l0); split2h(v1,h1,l1);
                if (z == 0) {
                    float2 o; o.x = v0; o.y = v1;
                    *(float2*)(g_q + (size_t)m * N + n) = o;
                    *(__half2*)(g_qh + (size_t)m * N + n) = __halves2half2(h0,h1);
                    *(__half2*)(g_ql + (size_t)m * N + n) = __halves2half2(l0,l1);
                } else {
                    *(__half2*)(g_k8h + (size_t)m * N + n) = __halves2half2(h0,h1);
                    *(__half2*)(g_k8l + (size_t)m * N + n) = __halves2half2(l0,l1);
                }
            }
        }
    }
}

// ===================== gemm1: 1-product (A single, B hi) ===================
template<bool RESID, bool GELU, bool OUTF, bool OUTS1, bool OUTT>
__global__ __launch_bounds__(256, 2) void gemm1(
    const __half* __restrict__ A, const __half* __restrict__ Bh,
    const float* __restrict__ bias, const float* __restrict__ R,
    float* __restrict__ C, __half* __restrict__ Ch,
    int M, int N, int K)
{
    extern __shared__ char sm[];
    constexpr int STGB = 2 * TILEB;
    const int tid  = threadIdx.x;
    const int wid  = tid >> 5, lane = tid & 31;
    const int warpM = wid & 1, warpN = wid >> 1;
    const int bm = blockIdx.y * 128, bn = blockIdx.x * 128;
    const uint32_t smb = smem_to_u32(sm);

    const int lrow   = tid >> 2;
    const int lchunk = tid & 3;
    const int soff   = lrow * TROW + lchunk * 16;
    const int a_off = (warpM * 64 + (lane & 15)) * TROW + (lane >> 4) * 16;
    const int b_off = (warpN * 32 + ((lane >> 4) << 3) + (lane & 7)) * TROW + ((lane >> 3) & 1) * 16;

    float acc[4][4][4];
    #pragma unroll
    for (int i = 0; i < 4; i++)
        #pragma unroll
        for (int j = 0; j < 4; j++)
            #pragma unroll
            for (int r = 0; r < 4; r++) acc[i][j][r] = 0.f;

    const int nch = K >> 5;
    auto issue = [&](int c, int s) {
        const int k0 = c << 5;
        const uint32_t st = smb + s * STGB;
        const __half* pa = A  + (size_t)(bm + lrow) * K + k0 + lchunk * 8;
        const __half* pb = Bh + (size_t)(bn + lrow) * K + k0 + lchunk * 8;
        cp16(st + soff, pa);         cp16(st + soff + 64*TROW, pa + (size_t)64*K);
        cp16(st + TILEB + soff, pb); cp16(st + TILEB + soff + 64*TROW, pb + (size_t)64*K);
        CP_COMMIT;
    };
    issue(0, 0);
    if (nch > 1) issue(1, 1);

    for (int c = 0; c < nch; ++c) {
        if (c + 1 < nch) { CP_WAIT1; } else { CP_WAIT0; }
        __syncthreads();
        if (c + 2 < nch) issue(c + 2, (c + 2) % 3);
        const uint32_t sb = smb + (c % 3) * STGB;
        #pragma unroll
        for (int ks = 0; ks < 2; ++ks) {
            uint32_t ar[4][4], bhr[2][4];
            #pragma unroll
            for (int i = 0; i < 4; ++i)
                ldsm4(ar[i], sb + a_off + i * (16 * TROW) + ks * 32);
            #pragma unroll
            for (int j = 0; j < 2; ++j)
                ldsm4(bhr[j], sb + TILEB + b_off + j * (16 * TROW) + ks * 32);
            #pragma unroll
            for (int i = 0; i < 4; ++i)
                #pragma unroll
                for (int j = 0; j < 4; ++j) {
                    uint32_t bfh[2] = { bhr[j >> 1][(j & 1) * 2], bhr[j >> 1][(j & 1) * 2 + 1] };
                    mma_f16(acc[i][j], ar[i], bfh);
                }
        }
    }

    #pragma unroll
    for (int i = 0; i < 4; ++i) {
        const int m0 = bm + warpM * 64 + i * 16 + (lane >> 2);
        #pragma unroll
        for (int j = 0; j < 4; ++j) {
            const int n = bn + warpN * 32 + j * 8 + (lane & 3) * 2;
            const float b0 = bias[n], b1 = bias[n + 1];
            #pragma unroll
            for (int rr = 0; rr < 2; ++rr) {
                const int m = m0 + rr * 8;
                float v0 = acc[i][j][rr*2+0] + b0;
                float v1 = acc[i][j][rr*2+1] + b1;
                if (RESID) {
                    const float2 rv = *(const float2*)(R + (size_t)m * N + n);
                    v0 += rv.x; v1 += rv.y;
                }
                if (GELU) {
                    v0 = 0.5f * v0 * (1.f + erff(v0 * 0.70710678118654752f));
                    v1 = 0.5f * v1 * (1.f + erff(v1 * 0.70710678118654752f));
                }
                if (OUTF) {
                    float2 o; o.x = v0; o.y = v1;
                    *(float2*)(C + (size_t)m * N + n) = o;
                }
                if (OUTS1) {
                    *(__half2*)(Ch + (size_t)m * N + n) =
                        __halves2half2(__float2half_rn(v0), __float2half_rn(v1));
                }
                if (OUTT) {
                    const int bb = m >> 9, tt = m & (T - 1);
                    const int hh = n >> 6, cc = n & (HS - 1);
                    size_t o0 = (((size_t)bb * H + hh) * HS + cc) * T + tt;
                    Ch[o0]     = __float2half_rn(v0);
                    Ch[o0 + T] = __float2half_rn(v1);
                }
            }
        }
    }
}

// ===================== mega1: rel (pipelined) + proj/ff wsplits =============
static constexpr int RELC_ROW = 272;
static constexpr int REL_STG  = 128 * RELC_ROW;       // 34816
static constexpr int REL_SMEM = 2048 + 2 * REL_STG;   // 71680

__device__ __forceinline__ void rel_body(char* sm, const float* __restrict__ relp,
                                         int t, int h)
{
    float4* qs4 = (float4*)sm;
    const uint32_t smb = smem_to_u32(sm);
    const int tid = threadIdx.x;
    const int v   = tid & 127;         // row within chunk
    const int bg  = tid >> 7;          // batch group: 0 -> b 0..3, 1 -> b 4..7

    if (tid < 128) {
        int b = tid >> 4, c4 = tid & 15;
        qs4[tid] = *(const float4*)(g_q + ((size_t)(b * T + t)) * D + h * HS + c4 * 4);
    }

    const float* relbase = relp + ((size_t)h * T + t) * T * HS;

    auto ldchunk = [&](int c, int s) {
        const uint32_t stage = smb + 2048 + s * REL_STG;
        #pragma unroll
        for (int i = 0; i < 8; ++i) {
            int idx = tid + 256 * i;        // 0..2047
            int r = idx >> 4;               // 0..127
            int u = idx & 15;
            cp16(stage + r * RELC_ROW + u * 16,
                 relbase + (size_t)(c * 128 + r) * HS + u * 4);
        }
        CP_COMMIT;
    };
    ldchunk(0, 0);
    ldchunk(1, 1);

    #pragma unroll
    for (int c = 0; c < 4; ++c) {
        if (c + 1 < 4) { CP_WAIT1; } else { CP_WAIT0; }
        __syncthreads();                   // chunk c ready (also orders qs4)
        const float4* row = (const float4*)(sm + 2048 + (c & 1) * REL_STG + v * RELC_ROW);
        float acc[4];
        #pragma unroll
        for (int bb = 0; bb < 4; bb++) acc[bb] = 0.f;
        #pragma unroll
        for (int c4 = 0; c4 < 16; ++c4) {
            float4 r = row[c4];
            #pragma unroll
            for (int bb = 0; bb < 4; bb++) {
                float4 q = qs4[(bg * 4 + bb) * 16 + c4];
                acc[bb] = fmaf(q.x, r.x, acc[bb]);
                acc[bb] = fmaf(q.y, r.y, acc[bb]);
                acc[bb] = fmaf(q.z, r.z, acc[bb]);
                acc[bb] = fmaf(q.w, r.w, acc[bb]);
            }
        }
        #pragma unroll
        for (int bb = 0; bb < 4; bb++) {
            const int b = bg * 4 + bb;
            g_rel[(((size_t)(b * H + h)) * T + t) * T + c * 128 + v] = __float2half_rn(acc[bb]);
        }
        __syncthreads();                   // stage (c&1) free for reuse
        if (c + 2 < 4) ldchunk(c + 2, c & 1);
    }
}

__device__ __forceinline__ void wsplit_body(char* smraw, const float* __restrict__ W,
    __half* __restrict__ Wh, int K, int N, int bx, int by)
{
    float (*tile)[33] = (float(*)[33])smraw;
    const int n0 = bx * 32, k0 = by * 32;
    const int tx = threadIdx.x & 31, ty = threadIdx.x >> 5;
    #pragma unroll
    for (int i = 0; i < 32; i += 8)
        tile[ty + i][tx] = W[(size_t)(k0 + ty + i) * N + n0 + tx];
    __syncthreads();
    #pragma unroll
    for (int i = 0; i < 32; i += 8) {
        float v = tile[tx][ty + i];
        Wh[(size_t)(n0 + ty + i) * K + k0 + tx] = __float2half_rn(v);
    }
}

__global__ __launch_bounds__(256) void mega1(
    const float* __restrict__ relp,
    const float* __restrict__ proj_w, const float* __restrict__ ff_w1,
    const float* __restrict__ ff_w2)
{
    extern __shared__ char sm[];
    const int bid = blockIdx.x;
    if (bid < 4096) {
        rel_body(sm, relp, bid & 511, bid >> 9);
    } else if (bid < 4352) {
        const int i = bid - 4096;   // proj: 16x16
        wsplit_body(sm, proj_w, g_pwh, D, D, i & 15, i >> 4);
    } else if (bid < 5376) {
        const int i = bid - 4352;   // ff1: K=D, N=FF (64 x 16)
        wsplit_body(sm, ff_w1, g_f1h, D, FF, i & 63, i >> 6);
    } else {
        const int i = bid - 5376;   // ff2: K=FF, N=D (16 x 64)
        wsplit_body(sm, ff_w2, g_f2h, FF, D, i & 15, i >> 4);
    }
}

// ===================== fused attention (flash-style, 2 CTAs/SM) =============
static constexpr int FB_QB   = 0;
static constexpr int FB_KB   = 20480;
static constexpr int FB_PB   = 61440;
static constexpr int FB_VB   = 81920;
static constexpr int FB_RED  = 102400;
static constexpr int FB_RM   = 103424;
static constexpr int FB_RL   = 103680;
static constexpr int FB_RF   = 103936;
static constexpr int FB_SMEM = 104192;

__global__ __launch_bounds__(256, 2) void fused_attn()
{
    extern __shared__ char sm[];
    const uint32_t smb = smem_to_u32(sm);
    float* wred  = (float*)(sm + FB_RED);
    float* row_m = (float*)(sm + FB_RM);
    float* row_l = (float*)(sm + FB_RL);
    float* row_f = (float*)(sm + FB_RF);
    const int tid = threadIdx.x;
    const int wid = tid >> 5, lane = tid & 31;
    const int warpM = wid & 1, warpN = wid >> 1;
    const int t0 = blockIdx.x * 64;
    const int bh = blockIdx.y;
    const int b = bh >> 3, h = bh & 7;

    if (tid < 64) { row_m[tid] = -1e30f; row_l[tid] = 0.f; }

    #pragma unroll
    for (int i = 0; i < 4; ++i) {
        int idx = tid + 256 * i;
        int tile = idx >> 8;
        int r    = (idx >> 2) & 63;
        int u    = idx & 3;
        const __half* src = (tile < 2 ? g_qh : g_ql)
            + (size_t)(b * T + t0 + r) * D + h * HS + (tile & 1) * 32 + u * 8;
        cp16(smb + FB_QB + tile * 5120 + r * 80 + u * 16, src);
    }
    CP_COMMIT;

    const uint32_t a_off  = FB_QB + (warpM * 32 + (lane & 15)) * 80 + (lane >> 4) * 16;
    const uint32_t b_off  = FB_KB + (warpN * 32 + ((lane >> 4) << 3) + (lane & 7)) * 80 + ((lane >> 3) & 1) * 16;
    const uint32_t pa_off = FB_PB + (warpM * 32 + (lane & 15)) * 80 + (lane >> 4) * 16;
    const uint32_t vb_off = FB_VB + (warpN * 16 + ((lane >> 4) << 3) + (lane & 7)) * 80 + ((lane >> 3) & 1) * 16;

    float oac[2][2][4];
    #pragma unroll
    for (int i = 0; i < 2; i++)
        #pragma unroll
        for (int j = 0; j < 2; j++)
            #pragma unroll
            for (int r = 0; r < 4; r++) oac[i][j][r] = 0.f;

    const int qrow0 = warpM * 32 + (lane >> 2);

    for (int nc = 0; nc < 4; ++nc) {
        __syncthreads();
        #pragma unroll
        for (int i = 0; i < 8; ++i) {
            int idx = tid + 256 * i;
            int tile = idx >> 9;
            int r    = (idx >> 2) & 127;
            int u    = idx & 3;
            const __half* src = (tile < 2 ? g_k8h : g_k8l)
                + (size_t)(b * T + nc * 128 + r) * D + h * HS + (tile & 1) * 32 + u * 8;
            cp16(smb + FB_KB + tile * 10240 + r * 80 + u * 16, src);
        }
        #pragma unroll
        for (int i = 0; i < 4; ++i) {
            int idx = tid + 256 * i;
            int sc  = idx >> 8;
            int r   = (idx >> 2) & 63;
            int u   = idx & 3;
            const __half* src = g_vth + (size_t)(bh * HS + r) * T + nc * 128 + sc * 32 + u * 8;
            cp16(smb + FB_VB + sc * 5120 + r * 80 + u * 16, src);
        }
        CP_COMMIT;
        CP_WAIT0;
        __syncthreads();

        float acc[2][4][4];
        #pragma unroll
        for (int i = 0; i < 2; i++)
            #pragma unroll
            for (int j = 0; j < 4; j++)
                #pragma unroll
                for (int r = 0; r < 4; r++) acc[i][j][r] = 0.f;

        #pragma unroll
        for (int kc = 0; kc < 2; ++kc) {
            #pragma unroll
            for (int ks = 0; ks < 2; ++ks) {
                uint32_t ahr[2][4], alr[2][4], bhr[2][4], blr[2][4];
                #pragma unroll
                for (int i = 0; i < 2; ++i) {
                    ldsm4(ahr[i], smb + a_off + kc * 5120 + i * (16*80) + ks * 32);
                    ldsm4(alr[i], smb + a_off + 10240 + kc * 5120 + i * (16*80) + ks * 32);
                }
                #pragma unroll
                for (int j = 0; j < 2; ++j) {
                    ldsm4(bhr[j], smb + b_off + kc * 10240 + j * (16*80) + ks * 32);
                    ldsm4(blr[j], smb + b_off + 20480 + kc * 10240 + j * (16*80) + ks * 32);
                }
                #pragma unroll
                for (int i = 0; i < 2; ++i)
                    #pragma unroll
                    for (int j = 0; j < 4; ++j) {
                        uint32_t bfh[2] = { bhr[j >> 1][(j & 1) * 2], bhr[j >> 1][(j & 1) * 2 + 1] };
                        uint32_t bfl[2] = { blr[j >> 1][(j & 1) * 2], blr[j >> 1][(j & 1) * 2 + 1] };
                        mma_f16(acc[i][j], ahr[i], bfh);
                        mma_f16(acc[i][j], ahr[i], bfl);
                        mma_f16(acc[i][j], alr[i], bfh);
                    }
            }
        }

        const __half* Rb = g_rel + ((size_t)bh * T + t0) * T;
        #pragma unroll
        for (int i = 0; i < 2; ++i)
            #pragma unroll
            for (int j = 0; j < 4; ++j)
                #pragma unroll
                for (int rr = 0; rr < 2; ++rr) {
                    const int row = qrow0 + i * 16 + rr * 8;
                    const int col = nc * 128 + warpN * 32 + j * 8 + (lane & 3) * 2;
                    __half2 rv = *(const __half2*)(Rb + (size_t)row * T + col);
                    acc[i][j][rr*2+0] += __half2float(rv.x);
                    acc[i][j][rr*2+1] += __half2float(rv.y);
                }

        float lm[2][2];
        #pragma unroll
        for (int i = 0; i < 2; ++i)
            #pragma unroll
            for (int rr = 0; rr < 2; ++rr) {
                float m = -1e30f;
                #pragma unroll
                for (int j = 0; j < 4; ++j)
                    m = fmaxf(m, fmaxf(acc[i][j][rr*2], acc[i][j][rr*2+1]));
                lm[i][rr] = m;
            }
        #pragma unroll
        for (int o = 1; o <= 2; o <<= 1) {
            #pragma unroll
            for (int i = 0; i < 2; ++i)
                #pragma unroll
                for (int rr = 0; rr < 2; ++rr)
                    lm[i][rr] = fmaxf(lm[i][rr], __shfl_xor_sync(0xffffffffu, lm[i][rr], o));
        }
        if ((lane & 3) == 0) {
            #pragma unroll
            for (int i = 0; i < 2; ++i)
                #pragma unroll
                for (int rr = 0; rr < 2; ++rr)
                    wred[warpN * 64 + qrow0 + i * 16 + rr * 8] = lm[i][rr];
        }
        __syncthreads();
        if (tid < 64) {
            float cm = fmaxf(fmaxf(wred[tid], wred[64 + tid]),
                             fmaxf(wred[128 + tid], wred[192 + tid]));
            float mo = row_m[tid];
            float mn = fmaxf(mo, cm);
            row_f[tid] = __expf(mo - mn);
            row_m[tid] = mn;
        }
        __syncthreads();

        float lsum[2][2];
        #pragma unroll
        for (int i = 0; i < 2; ++i)
            #pragma unroll
            for (int rr = 0; rr < 2; ++rr) {
                const int row = qrow0 + i * 16 + rr * 8;
                const float mn = row_m[row];
                float s = 0.f;
                #pragma unroll
                for (int j = 0; j < 4; ++j) {
                    float p0 = __expf(acc[i][j][rr*2+0] - mn);
                    float p1 = __expf(acc[i][j][rr*2+1] - mn);
                    s += p0 + p1;
                    *(__half2*)(sm + FB_PB + warpN * 5120 + row * 80
                                + (j * 8 + (lane & 3) * 2) * 2) =
                        __halves2half2(__float2half_rn(p0), __float2half_rn(p1));
                }
                lsum[i][rr] = s;
            }
        #pragma unroll
        for (int o = 1; o <= 2; o <<= 1) {
            #pragma unroll
            for (int i = 0; i < 2; ++i)
                #pragma unroll
                for (int rr = 0; rr < 2; ++rr)
                    lsum[i][rr] += __shfl_xor_sync(0xffffffffu, lsum[i][rr], o);
        }
        __syncthreads();
        if ((lane & 3) == 0) {
            #pragma unroll
            for (int i = 0; i < 2; ++i)
                #pragma unroll
                for (int rr = 0; rr < 2; ++rr)
                    wred[warpN * 64 + qrow0 + i * 16 + rr * 8] = lsum[i][rr];
        }
        __syncthreads();
        if (tid < 64) {
            float cs = wred[tid] + wred[64 + tid] + wred[128 + tid] + wred[192 + tid];
            row_l[tid] = row_l[tid] * row_f[tid] + cs;
        }

        #pragma unroll
        for (int i = 0; i < 2; ++i)
            #pragma unroll
            for (int rr = 0; rr < 2; ++rr) {
                const float f = row_f[qrow0 + i * 16 + rr * 8];
                #pragma unroll
                for (int j = 0; j < 2; ++j) {
                    oac[i][j][rr*2+0] *= f;
                    oac[i][j][rr*2+1] *= f;
                }
            }
        #pragma unroll
        for (int c2 = 0; c2 < 4; ++c2) {
            #pragma unroll
            for (int ks = 0; ks < 2; ++ks) {
                uint32_t ar[2][4], vh4[4];
                #pragma unroll
                for (int i = 0; i < 2; ++i)
                    ldsm4(ar[i], smb + pa_off + c2 * 5120 + i * (16*80) + ks * 32);
                ldsm4(vh4, smb + vb_off + c2 * 5120 + ks * 32);
                #pragma unroll
                for (int i = 0; i < 2; ++i)
                    #pragma unroll
                    for (int j = 0; j < 2; ++j) {
                        uint32_t bfh[2] = { vh4[j * 2], vh4[j * 2 + 1] };
                        mma_f16(oac[i][j], ar[i], bfh);
                    }
            }
        }
    }

    __syncthreads();
    #pragma unroll
    for (int i = 0; i < 2; ++i)
        #pragma unroll
        for (int rr = 0; rr < 2; ++rr) {
            const int m = t0 + qrow0 + i * 16 + rr * 8;
            const float inv = 1.f / row_l[qrow0 + i * 16 + rr * 8];
            #pragma unroll
            for (int j = 0; j < 2; ++j) {
                const int cc = warpN * 16 + j * 8 + (lane & 3) * 2;
                *(__half2*)(g_att + (size_t)(b * T + m) * D + h * HS + cc) =
                    __halves2half2(__float2half_rn(oac[i][j][rr*2+0] * inv),
                                   __float2half_rn(oac[i][j][rr*2+1] * inv));
            }
        }
}

// ===================== launch ==============================================
extern "C" void kernel_launch(void* const* d_in, const int* in_sizes, int n_in,
                              void* d_out, int out_size)
{
    (void)in_sizes; (void)n_in; (void)out_size;
    const float* src    = (const float*)d_in[0];
    const float* norm_w = (const float*)d_in[1];
    const float* Wq     = (const float*)d_in[2];
    const float* bq     = (const float*)d_in[3];
    const float* Wk     = (const float*)d_in[4];
    const float* bk     = (const float*)d_in[5];
    const float* Wv     = (const float*)d_in[6];
    const float* bv     = (const float*)d_in[7];
    const float* relp   = (const float*)d_in[8];
    const float* proj_w = (const float*)d_in[9];
    const float* proj_b = (const float*)d_in[10];
    const float* ff_w1  = (const float*)d_in[11];
    const float* ff_b1  = (const float*)d_in[12];
    const float* ff_w2  = (const float*)d_in[13];
    const float* ff_b2  = (const float*)d_in[14];
    float* out = (float*)d_out;

    float *px, *psrc2, *py;
    __half *pxh, *pyh, *pvth, *patt, *phid;
    __half *ppwh, *pf1h, *pf2h, *pw3h;
    cudaGetSymbolAddress((void**)&px,    g_x);
    cudaGetSymbolAddress((void**)&psrc2, g_src2);
    cudaGetSymbolAddress((void**)&py,    g_y);
    cudaGetSymbolAddress((void**)&pxh,   g_xh);
    cudaGetSymbolAddress((void**)&pyh,   g_yh);
    cudaGetSymbolAddress((void**)&pvth,  g_vth);
    cudaGetSymbolAddress((void**)&patt,  g_att);
    cudaGetSymbolAddress((void**)&phid,  g_hid);
    cudaGetSymbolAddress((void**)&pw3h,  g_w3h);
    cudaGetSymbolAddress((void**)&ppwh,  g_pwh);
    cudaGetSymbolAddress((void**)&pf1h,  g_f1h);
    cudaGetSymbolAddress((void**)&pf2h,  g_f2h);

    cudaFuncSetAttribute(gemm_qk, cudaFuncAttributeMaxDynamicSharedMemorySize, G3_SMEM);
    cudaFuncSetAttribute(gemm1<false,false,false,false,true>,  cudaFuncAttributeMaxDynamicSharedMemorySize, G1_SMEM);
    cudaFuncSetAttribute(gemm1<true, false,true, false,false>, cudaFuncAttributeMaxDynamicSharedMemorySize, G1_SMEM);
    cudaFuncSetAttribute(gemm1<false,true, false,true, false>, cudaFuncAttributeMaxDynamicSharedMemorySize, G1_SMEM);
    cudaFuncSetAttribute(mega1, cudaFuncAttributeMaxDynamicSharedMemorySize, REL_SMEM);
    cudaFuncSetAttribute(fused_attn, cudaFuncAttributeMaxDynamicSharedMemorySize, FB_SMEM);

    // 1. qkv weight transpose (768) + rmsnorm(x) (2048 CTAs x 2 rows) fused
    mega0<<<768 + 2048, 256>>>(Wq, Wk, Wv, src, norm_w);

    // 2. q (fp32 + hi/lo) and k8 (hi/lo) in one launch (3-product, 2 CTAs/SM)
    gemm_qk<<<dim3(D/128, BT/128, 2), 256, G3_SMEM>>>(bq, bk);

    // 3. v: transposed single fp16 (1-product)
    gemm1<false,false,false,false,true><<<dim3(D/128, BT/128), 256, G1_SMEM>>>(
        pxh, pw3h + 2*D*D, bv, nullptr, nullptr, pvth, BT, D, D);

    // 4. rel (pipelined, DRAM umbrella) + proj/ff weight transposes, overlapped
    mega1<<<4096 + 2304, 256, REL_SMEM>>>(relp, proj_w, ff_w1, ff_w2);

    // 5. flash attention (scores + rel + online softmax + AV)
    fused_attn<<<dim3(T/64, BATCH*H), 256, FB_SMEM>>>();

    // 6. src2 = x + att @ proj_w + proj_b
    gemm1<true,false,true,false,false><<<dim3(D/128, BT/128), 256, G1_SMEM>>>(
        patt, ppwh, proj_b, px, psrc2, nullptr, BT, D, D);

    // 7. y = rmsnorm(src2)
    rmsnorm_kernel<<<BT, 128>>>(psrc2, norm_w, py, pyh);

    // 8. h = gelu(y @ ff_w1 + ff_b1)
    gemm1<false,true,false,true,false><<<dim3(FF/128, BT/128), 256, G1_SMEM>>>(
        pyh, pf1h, ff_b1, nullptr, nullptr, phid, BT, FF, D);

    // 9. out = y + h @ ff_w2 + ff_b2
    gemm1<true,false,true,false,false><<<dim3(D/128, BT/128), 256, G1_SMEM>>>(
        phid, pf2h, ff_b2, py, out, nullptr, BT, D, FF);
}

// round 16
// speedup vs baseline: 1.0277x; 1.0277x over previous
#include <cuda_runtime.h>
#include <cuda_fp16.h>
#include <math.h>
#include <stdint.h>

#define BATCH 8
#define T 512
#define D 512
#define H 8
#define HS 64
#define BT (BATCH*T)     // 4096
#define FF 2048

// ===================== device scratch =====================
__device__ __align__(16) float g_x[BT*D];
__device__ __align__(16) float g_q[BT*D];
__device__ __align__(16) float g_src2[BT*D];
__device__ __align__(16) float g_y[BT*D];
__device__ __align__(16) __half g_rel[BATCH*H*T*T];     // 32MB
__device__ __align__(16) __half g_xh[BT*D], g_xl[BT*D];
__device__ __align__(16) __half g_yh[BT*D];
__device__ __align__(16) __half g_qh[BT*D], g_ql[BT*D];
__device__ __align__(16) __half g_k8h[BT*D], g_k8l[BT*D];
__device__ __align__(16) __half g_vth[BATCH*H*HS*T];
__device__ __align__(16) __half g_att[BT*D];
__device__ __align__(16) __half g_hid[BT*FF];
__device__ __align__(16) __half g_w3h[3*D*D], g_w3l[3*D*D];
__device__ __align__(16) __half g_pwh[D*D];
__device__ __align__(16) __half g_f1h[FF*D];
__device__ __align__(16) __half g_f2h[D*FF];

__device__ __forceinline__ void split2h(float v, __half& h, __half& l) {
    h = __float2half_rn(v);
    l = __float2half_rn(v - __half2float(h));
}

// ===================== primitives =====================
__device__ __forceinline__ void mma_f16(float* d, const uint32_t* a, const uint32_t* b) {
    asm volatile(
        "mma.sync.aligned.m16n8k16.row.col.f32.f16.f16.f32 "
        "{%0,%1,%2,%3}, {%4,%5,%6,%7}, {%8,%9}, {%0,%1,%2,%3};"
        : "+f"(d[0]), "+f"(d[1]), "+f"(d[2]), "+f"(d[3])
        : "r"(a[0]), "r"(a[1]), "r"(a[2]), "r"(a[3]), "r"(b[0]), "r"(b[1]));
}
__device__ __forceinline__ void ldsm4(uint32_t* r, uint32_t addr) {
    asm volatile("ldmatrix.sync.aligned.m8n8.x4.shared.b16 {%0,%1,%2,%3}, [%4];"
        : "=r"(r[0]), "=r"(r[1]), "=r"(r[2]), "=r"(r[3]) : "r"(addr));
}
__device__ __forceinline__ uint32_t smem_to_u32(const void* p) {
    uint32_t a;
    asm("{ .reg .u64 t; cvta.to.shared.u64 t, %1; cvt.u32.u64 %0, t; }" : "=r"(a) : "l"(p));
    return a;
}
__device__ __forceinline__ void cp16(uint32_t s, const void* g) {
    asm volatile("{.reg .u64 gp; cvta.to.global.u64 gp, %1; cp.async.cg.shared.global [%0], [gp], 16;}"
        :: "r"(s), "l"(g) : "memory");
}
#define CP_COMMIT asm volatile("cp.async.commit_group;" ::: "memory")
#define CP_WAIT1  asm volatile("cp.async.wait_group 1;" ::: "memory")
#define CP_WAIT0  asm volatile("cp.async.wait_group 0;" ::: "memory")

// ===================== mega0: qkv wsplit + rmsnorm(x) =====================
__device__ __forceinline__ void wsplit_qkv_body(
    const float* __restrict__ Wq, const float* __restrict__ Wk, const float* __restrict__ Wv,
    float (*tile)[33], int bx, int by, int bz)
{
    const int mat = bz >> 3, h = bz & 7;
    const int c0 = by * 32, d0 = bx * 32;
    const int tx = threadIdx.x & 31, ty = threadIdx.x >> 5;
    const float* W = (mat == 0) ? Wq : (mat == 1) ? Wk : Wv;
    #pragma unroll
    for (int i = 0; i < 32; i += 8)
        tile[ty + i][tx] = W[((size_t)h * D + d0 + ty + i) * HS + c0 + tx];
    __syncthreads();
    #pragma unroll
    for (int i = 0; i < 32; i += 8) {
        float v = tile[tx][ty + i];
        __half hh, ll; split2h(v, hh, ll);
        size_t o = (size_t)mat * D * D + (size_t)(h * HS + c0 + ty + i) * D + d0 + tx;
        g_w3h[o] = hh; g_w3l[o] = ll;
    }
}

__device__ __forceinline__ void rmsnorm2_body(const float* __restrict__ in,
    const float* __restrict__ w, int row0,
    float* __restrict__ out, __half* __restrict__ outh, __half* __restrict__ outl,
    float* ws)
{
    const int tid = threadIdx.x;
    const int half = tid >> 7;
    const int t7 = tid & 127;
    const int row = row0 + half;
    const float4 v = ((const float4*)(in + (size_t)row * D))[t7];
    float ss = v.x*v.x + v.y*v.y + v.z*v.z + v.w*v.w;
    #pragma unroll
    for (int o = 16; o > 0; o >>= 1) ss += __shfl_xor_sync(0xffffffffu, ss, o);
    if ((tid & 31) == 0) ws[tid >> 5] = ss;
    __syncthreads();
    const float total = ws[half*4+0] + ws[half*4+1] + ws[half*4+2] + ws[half*4+3];
    const float r = rsqrtf(total * (1.0f / (float)D) + 1e-6f);
    const float4 wv = ((const float4*)w)[t7];
    float4 o;
    o.x = v.x * r * wv.x; o.y = v.y * r * wv.y;
    o.z = v.z * r * wv.z; o.w = v.w * r * wv.w;
    ((float4*)(out + (size_t)row * D))[t7] = o;
    __half h0,l0,h1,l1,h2,l2,h3,l3;
    split2h(o.x,h0,l0); split2h(o.y,h1,l1); split2h(o.z,h2,l2); split2h(o.w,h3,l3);
    size_t base = (size_t)row * D + t7 * 4;
    *(__half2*)(outh + base)     = __halves2half2(h0,h1);
    *(__half2*)(outh + base + 2) = __halves2half2(h2,h3);
    if (outl) {
        *(__half2*)(outl + base)     = __halves2half2(l0,l1);
        *(__half2*)(outl + base + 2) = __halves2half2(l2,l3);
    }
}

__global__ __launch_bounds__(256) void mega0(
    const float* __restrict__ Wq, const float* __restrict__ Wk, const float* __restrict__ Wv,
    const float* __restrict__ src, const float* __restrict__ norm_w)
{
    __shared__ float tile[32][33];
    __shared__ float ws[8];
    const int bid = blockIdx.x;
    if (bid < 768) {
        wsplit_qkv_body(Wq, Wk, Wv, tile, bid & 15, (bid >> 4) & 1, bid >> 5);
    } else {
        rmsnorm2_body(src, norm_w, (bid - 768) * 2, g_x, g_xh, g_xl, ws);
    }
}

// ===================== rmsnorm (single, for y) =====================
__global__ __launch_bounds__(128) void rmsnorm_kernel(
    const float* __restrict__ in, const float* __restrict__ w,
    float* __restrict__ out, __half* __restrict__ outh)
{
    int row = blockIdx.x;
    int tid = threadIdx.x;
    const float4 v = ((const float4*)(in + (size_t)row * D))[tid];
    float ss = v.x*v.x + v.y*v.y + v.z*v.z + v.w*v.w;
    #pragma unroll
    for (int o = 16; o > 0; o >>= 1) ss += __shfl_xor_sync(0xffffffffu, ss, o);
    __shared__ float ws[4];
    if ((tid & 31) == 0) ws[tid >> 5] = ss;
    __syncthreads();
    float total = ws[0] + ws[1] + ws[2] + ws[3];
    float r = rsqrtf(total * (1.0f / (float)D) + 1e-6f);
    const float4 wv = ((const float4*)w)[tid];
    float4 o;
    o.x = v.x * r * wv.x; o.y = v.y * r * wv.y;
    o.z = v.z * r * wv.z; o.w = v.w * r * wv.w;
    ((float4*)(out + (size_t)row * D))[tid] = o;
    size_t base = (size_t)row * D + tid * 4;
    *(__half2*)(outh + base)     = __halves2half2(__float2half_rn(o.x), __float2half_rn(o.y));
    *(__half2*)(outh + base + 2) = __halves2half2(__float2half_rn(o.z), __float2half_rn(o.w));
}

// ===================== tile constants =====================
static constexpr int TROW  = 80;
static constexpr int TILEB = 128 * TROW;      // 10240
static constexpr int G1_SMEM = 3 * 2 * TILEB; // 61440
static constexpr int G3_STG  = 4 * TILEB;     // 40960
static constexpr int G3_SMEM = 2 * G3_STG;    // 81920  (2-stage -> 2 CTAs/SM)

// ===================== merged q/k GEMM (3-product, 2-stage, 2 CTAs/SM) =====
__global__ __launch_bounds__(256, 2) void gemm_qk(
    const float* __restrict__ bq, const float* __restrict__ bk)
{
    extern __shared__ char sm[];
    const int z = blockIdx.z;               // 0: q, 1: k8
    const __half* Ah = g_xh;
    const __half* Al = g_xl;
    const __half* Bh = g_w3h + (size_t)z * D * D;
    const __half* Bl = g_w3l + (size_t)z * D * D;
    const float* bias = z ? bk : bq;
    const float osc = z ? 8.f : 1.f;
    const int K = D, N = D;

    const int tid  = threadIdx.x;
    const int wid  = tid >> 5, lane = tid & 31;
    const int warpM = wid & 1, warpN = wid >> 1;
    const int bm = blockIdx.y * 128, bn = blockIdx.x * 128;
    const uint32_t smb = smem_to_u32(sm);

    const int lrow   = tid >> 2;
    const int lchunk = tid & 3;
    const int soff   = lrow * TROW + lchunk * 16;
    const int a_off = (warpM * 64 + (lane & 15)) * TROW + (lane >> 4) * 16;
    const int b_off = (warpN * 32 + ((lane >> 4) << 3) + (lane & 7)) * TROW + ((lane >> 3) & 1) * 16;

    float acc[4][4][4];
    #pragma unroll
    for (int i = 0; i < 4; i++)
        #pragma unroll
        for (int j = 0; j < 4; j++)
            #pragma unroll
            for (int r = 0; r < 4; r++) acc[i][j][r] = 0.f;

    const int nch = K >> 5;
    auto issue = [&](int c, int s) {
        const int k0 = c << 5;
        const uint32_t st = smb + s * G3_STG;
        const __half* pa  = Ah + (size_t)(bm + lrow) * K + k0 + lchunk * 8;
        const __half* pal = Al + (size_t)(bm + lrow) * K + k0 + lchunk * 8;
        const __half* pb  = Bh + (size_t)(bn + lrow) * K + k0 + lchunk * 8;
        const __half* pbl = Bl + (size_t)(bn + lrow) * K + k0 + lchunk * 8;
        cp16(st + soff, pa);            cp16(st + soff + 64*TROW, pa + (size_t)64*K);
        cp16(st + TILEB + soff, pal);   cp16(st + TILEB + soff + 64*TROW, pal + (size_t)64*K);
        cp16(st + 2*TILEB + soff, pb);  cp16(st + 2*TILEB + soff + 64*TROW, pb + (size_t)64*K);
        cp16(st + 3*TILEB + soff, pbl); cp16(st + 3*TILEB + soff + 64*TROW, pbl + (size_t)64*K);
        CP_COMMIT;
    };
    issue(0, 0);
    issue(1, 1);

    for (int c = 0; c < nch; ++c) {
        if (c + 1 < nch) { CP_WAIT1; } else { CP_WAIT0; }
        __syncthreads();
        const uint32_t sb = smb + (c & 1) * G3_STG;
        #pragma unroll
        for (int ks = 0; ks < 2; ++ks) {
            uint32_t ahr[4][4], alr[4][4], bhr[2][4], blr[2][4];
            #pragma unroll
            for (int i = 0; i < 4; ++i) {
                ldsm4(ahr[i], sb + a_off + i * (16 * TROW) + ks * 32);
                ldsm4(alr[i], sb + TILEB + a_off + i * (16 * TROW) + ks * 32);
            }
            #pragma unroll
            for (int j = 0; j < 2; ++j) {
                ldsm4(bhr[j], sb + 2*TILEB + b_off + j * (16 * TROW) + ks * 32);
                ldsm4(blr[j], sb + 3*TILEB + b_off + j * (16 * TROW) + ks * 32);
            }
            #pragma unroll
            for (int i = 0; i < 4; ++i)
                #pragma unroll
                for (int j = 0; j < 4; ++j) {
                    uint32_t bfh[2] = { bhr[j >> 1][(j & 1) * 2], bhr[j >> 1][(j & 1) * 2 + 1] };
                    uint32_t bfl[2] = { blr[j >> 1][(j & 1) * 2], blr[j >> 1][(j & 1) * 2 + 1] };
                    mma_f16(acc[i][j], ahr[i], bfh);
                    mma_f16(acc[i][j], ahr[i], bfl);
                    mma_f16(acc[i][j], alr[i], bfh);
                }
        }
        __syncthreads();
        if (c + 2 < nch) issue(c + 2, c & 1);
    }

    #pragma unroll
    for (int i = 0; i < 4; ++i) {
        const int m0 = bm + warpM * 64 + i * 16 + (lane >> 2);
        #pragma unroll
        for (int j = 0; j < 4; ++j) {
            const int n = bn + warpN * 32 + j * 8 + (lane & 3) * 2;
            const float b0 = bias[n], b1 = bias[n + 1];
            #pragma unroll
            for (int rr = 0; rr < 2; ++rr) {
                const int m = m0 + rr * 8;
                float v0 = (acc[i][j][rr*2+0] + b0) * osc;
                float v1 = (acc[i][j][rr*2+1] + b1) * osc;
                __half h0,l0,h1,l1;
                split2h(v0,h0,l0); split2h(v1,h1,l1);
                if (z == 0) {
                    float2 o; o.x = v0; o.y = v1;
                    *(float2*)(g_q + (size_t)m * N + n) = o;
                    *(__half2*)(g_qh + (size_t)m * N + n) = __halves2half2(h0,h1);
                    *(__half2*)(g_ql + (size_t)m * N + n) = __halves2half2(l0,l1);
                } else {
                    *(__half2*)(g_k8h + (size_t)m * N + n) = __halves2half2(h0,h1);
                    *(__half2*)(g_k8l + (size_t)m * N + n) = __halves2half2(l0,l1);
                }
            }
        }
    }
}

// ===================== gemm1: 1-product (A single, B hi) ===================
template<bool RESID, bool GELU, bool OUTF, bool OUTS1, bool OUTT>
__global__ __launch_bounds__(256, 2) void gemm1(
    const __half* __restrict__ A, const __half* __restrict__ Bh,
    const float* __restrict__ bias, const float* __restrict__ R,
    float* __restrict__ C, __half* __restrict__ Ch,
    int M, int N, int K)
{
    extern __shared__ char sm[];
    constexpr int STGB = 2 * TILEB;
    const int tid  = threadIdx.x;
    const int wid  = tid >> 5, lane = tid & 31;
    const int warpM = wid & 1, warpN = wid >> 1;
    const int bm = blockIdx.y * 128, bn = blockIdx.x * 128;
    const uint32_t smb = smem_to_u32(sm);

    const int lrow   = tid >> 2;
    const int lchunk = tid & 3;
    const int soff   = lrow * TROW + lchunk * 16;
    const int a_off = (warpM * 64 + (lane & 15)) * TROW + (lane >> 4) * 16;
    const int b_off = (warpN * 32 + ((lane >> 4) << 3) + (lane & 7)) * TROW + ((lane >> 3) & 1) * 16;

    float acc[4][4][4];
    #pragma unroll
    for (int i = 0; i < 4; i++)
        #pragma unroll
        for (int j = 0; j < 4; j++)
            #pragma unroll
            for (int r = 0; r < 4; r++) acc[i][j][r] = 0.f;

    const int nch = K >> 5;
    auto issue = [&](int c, int s) {
        const int k0 = c << 5;
        const uint32_t st = smb + s * STGB;
        const __half* pa = A  + (size_t)(bm + lrow) * K + k0 + lchunk * 8;
        const __half* pb = Bh + (size_t)(bn + lrow) * K + k0 + lchunk * 8;
        cp16(st + soff, pa);         cp16(st + soff + 64*TROW, pa + (size_t)64*K);
        cp16(st + TILEB + soff, pb); cp16(st + TILEB + soff + 64*TROW, pb + (size_t)64*K);
        CP_COMMIT;
    };
    issue(0, 0);
    if (nch > 1) issue(1, 1);

    for (int c = 0; c < nch; ++c) {
        if (c + 1 < nch) { CP_WAIT1; } else { CP_WAIT0; }
        __syncthreads();
        if (c + 2 < nch) issue(c + 2, (c + 2) % 3);
        const uint32_t sb = smb + (c % 3) * STGB;
        #pragma unroll
        for (int ks = 0; ks < 2; ++ks) {
            uint32_t ar[4][4], bhr[2][4];
            #pragma unroll
            for (int i = 0; i < 4; ++i)
                ldsm4(ar[i], sb + a_off + i * (16 * TROW) + ks * 32);
            #pragma unroll
            for (int j = 0; j < 2; ++j)
                ldsm4(bhr[j], sb + TILEB + b_off + j * (16 * TROW) + ks * 32);
            #pragma unroll
            for (int i = 0; i < 4; ++i)
                #pragma unroll
                for (int j = 0; j < 4; ++j) {
                    uint32_t bfh[2] = { bhr[j >> 1][(j & 1) * 2], bhr[j >> 1][(j & 1) * 2 + 1] };
                    mma_f16(acc[i][j], ar[i], bfh);
                }
        }
    }

    #pragma unroll
    for (int i = 0; i < 4; ++i) {
        const int m0 = bm + warpM * 64 + i * 16 + (lane >> 2);
        #pragma unroll
        for (int j = 0; j < 4; ++j) {
            const int n = bn + warpN * 32 + j * 8 + (lane & 3) * 2;
            const float b0 = bias[n], b1 = bias[n + 1];
            #pragma unroll
            for (int rr = 0; rr < 2; ++rr) {
                const int m = m0 + rr * 8;
                float v0 = acc[i][j][rr*2+0] + b0;
                float v1 = acc[i][j][rr*2+1] + b1;
                if (RESID) {
                    const float2 rv = *(const float2*)(R + (size_t)m * N + n);
                    v0 += rv.x; v1 += rv.y;
                }
                if (GELU) {
                    v0 = 0.5f * v0 * (1.f + erff(v0 * 0.70710678118654752f));
                    v1 = 0.5f * v1 * (1.f + erff(v1 * 0.70710678118654752f));
                }
                if (OUTF) {
                    float2 o; o.x = v0; o.y = v1;
                    *(float2*)(C + (size_t)m * N + n) = o;
                }
                if (OUTS1) {
                    *(__half2*)(Ch + (size_t)m * N + n) =
                        __halves2half2(__float2half_rn(v0), __float2half_rn(v1));
                }
                if (OUTT) {
                    const int bb = m >> 9, tt = m & (T - 1);
                    const int hh = n >> 6, cc = n & (HS - 1);
                    size_t o0 = (((size_t)bb * H + hh) * HS + cc) * T + tt;
                    Ch[o0]     = __float2half_rn(v0);
                    Ch[o0 + T] = __float2half_rn(v1);
                }
            }
        }
    }
}

// ===================== mega1: rel (R14 body) + proj/ff wsplits ==============
static constexpr int REL_ROW  = 272;
static constexpr int REL_SMEM = 2048 + 256 * REL_ROW;  // 71680

__device__ __forceinline__ void rel_body(char* sm, const float* __restrict__ relp,
                                         int t, int h)
{
    float4* qs4 = (float4*)sm;
    const uint32_t smb = smem_to_u32(sm);
    const uint32_t stage = smb + 2048;
    const int tid = threadIdx.x;

    if (tid < 128) {
        int b = tid >> 4, c4 = tid & 15;
        qs4[tid] = *(const float4*)(g_q + ((size_t)(b * T + t)) * D + h * HS + c4 * 4);
    }

    const float* relbase = relp + ((size_t)h * T + t) * T * HS;

    #pragma unroll
    for (int pass = 0; pass < 2; ++pass) {
        const int vbase = pass * 256;
        #pragma unroll
        for (int i = 0; i < 16; ++i) {
            int idx = tid + 256 * i;
            int v = idx >> 4;
            int c = idx & 15;
            cp16(stage + v * REL_ROW + c * 16,
                 relbase + (size_t)(vbase + v) * HS + c * 4);
        }
        CP_COMMIT;
        CP_WAIT0;
        __syncthreads();

        const float4* row = (const float4*)(sm + 2048 + tid * REL_ROW);
        float acc[8];
        #pragma unroll
        for (int b = 0; b < 8; b++) acc[b] = 0.f;
        #pragma unroll
        for (int c4 = 0; c4 < 16; ++c4) {
            float4 r = row[c4];
            #pragma unroll
            for (int b = 0; b < 8; b++) {
                float4 q = qs4[b * 16 + c4];
                acc[b] = fmaf(q.x, r.x, acc[b]);
                acc[b] = fmaf(q.y, r.y, acc[b]);
                acc[b] = fmaf(q.z, r.z, acc[b]);
                acc[b] = fmaf(q.w, r.w, acc[b]);
            }
        }
        #pragma unroll
        for (int b = 0; b < 8; b++)
            g_rel[(((size_t)(b * H + h)) * T + t) * T + vbase + tid] = __float2half_rn(acc[b]);
        __syncthreads();
    }
}

__device__ __forceinline__ void wsplit_body(char* smraw, const float* __restrict__ W,
    __half* __restrict__ Wh, int K, int N, int bx, int by)
{
    float (*tile)[33] = (float(*)[33])smraw;
    const int n0 = bx * 32, k0 = by * 32;
    const int tx = threadIdx.x & 31, ty = threadIdx.x >> 5;
    #pragma unroll
    for (int i = 0; i < 32; i += 8)
        tile[ty + i][tx] = W[(size_t)(k0 + ty + i) * N + n0 + tx];
    __syncthreads();
    #pragma unroll
    for (int i = 0; i < 32; i += 8) {
        float v = tile[tx][ty + i];
        Wh[(size_t)(n0 + ty + i) * K + k0 + tx] = __float2half_rn(v);
    }
}

__global__ __launch_bounds__(256) void mega1(
    const float* __restrict__ relp,
    const float* __restrict__ proj_w, const float* __restrict__ ff_w1,
    const float* __restrict__ ff_w2)
{
    extern __shared__ char sm[];
    const int bid = blockIdx.x;
    if (bid < 4096) {
        rel_body(sm, relp, bid & 511, bid >> 9);
    } else if (bid < 4352) {
        const int i = bid - 4096;   // proj: 16x16
        wsplit_body(sm, proj_w, g_pwh, D, D, i & 15, i >> 4);
    } else if (bid < 5376) {
        const int i = bid - 4352;   // ff1: K=D, N=FF (64 x 16)
        wsplit_body(sm, ff_w1, g_f1h, D, FF, i & 63, i >> 6);
    } else {
        const int i = bid - 5376;   // ff2: K=FF, N=D (16 x 64)
        wsplit_body(sm, ff_w2, g_f2h, FF, D, i & 15, i >> 4);
    }
}

// ===================== fused attention (flash-style, 2 CTAs/SM) =============
static constexpr int FB_QB   = 0;
static constexpr int FB_KB   = 20480;
static constexpr int FB_PB   = 61440;
static constexpr int FB_VB   = 81920;
static constexpr int FB_RED  = 102400;
static constexpr int FB_RM   = 103424;
static constexpr int FB_RL   = 103680;
static constexpr int FB_RF   = 103936;
static constexpr int FB_SMEM = 104192;

__global__ __launch_bounds__(256, 2) void fused_attn()
{
    extern __shared__ char sm[];
    const uint32_t smb = smem_to_u32(sm);
    float* wred  = (float*)(sm + FB_RED);
    float* row_m = (float*)(sm + FB_RM);
    float* row_l = (float*)(sm + FB_RL);
    float* row_f = (float*)(sm + FB_RF);
    const int tid = threadIdx.x;
    const int wid = tid >> 5, lane = tid & 31;
    const int warpM = wid & 1, warpN = wid >> 1;
    const int t0 = blockIdx.x * 64;
    const int bh = blockIdx.y;
    const int b = bh >> 3, h = bh & 7;

    if (tid < 64) { row_m[tid] = -1e30f; row_l[tid] = 0.f; }

    #pragma unroll
    for (int i = 0; i < 4; ++i) {
        int idx = tid + 256 * i;
        int tile = idx >> 8;
        int r    = (idx >> 2) & 63;
        int u    = idx & 3;
        const __half* src = (tile < 2 ? g_qh : g_ql)
            + (size_t)(b * T + t0 + r) * D + h * HS + (tile & 1) * 32 + u * 8;
        cp16(smb + FB_QB + tile * 5120 + r * 80 + u * 16, src);
    }
    CP_COMMIT;

    const uint32_t a_off  = FB_QB + (warpM * 32 + (lane & 15)) * 80 + (lane >> 4) * 16;
    const uint32_t b_off  = FB_KB + (warpN * 32 + ((lane >> 4) << 3) + (lane & 7)) * 80 + ((lane >> 3) & 1) * 16;
    const uint32_t pa_off = FB_PB + (warpM * 32 + (lane & 15)) * 80 + (lane >> 4) * 16;
    const uint32_t vb_off = FB_VB + (warpN * 16 + ((lane >> 4) << 3) + (lane & 7)) * 80 + ((lane >> 3) & 1) * 16;

    float oac[2][2][4];
    #pragma unroll
    for (int i = 0; i < 2; i++)
        #pragma unroll
        for (int j = 0; j < 2; j++)
            #pragma unroll
            for (int r = 0; r < 4; r++) oac[i][j][r] = 0.f;

    const int qrow0 = warpM * 32 + (lane >> 2);

    for (int nc = 0; nc < 4; ++nc) {
        __syncthreads();
        #pragma unroll
        for (int i = 0; i < 8; ++i) {
            int idx = tid + 256 * i;
            int tile = idx >> 9;
            int r    = (idx >> 2) & 127;
            int u    = idx & 3;
            const __half* src = (tile < 2 ? g_k8h : g_k8l)
                + (size_t)(b * T + nc * 128 + r) * D + h * HS + (tile & 1) * 32 + u * 8;
            cp16(smb + FB_KB + tile * 10240 + r * 80 + u * 16, src);
        }
        #pragma unroll
        for (int i = 0; i < 4; ++i) {
            int idx = tid + 256 * i;
            int sc  = idx >> 8;
            int r   = (idx >> 2) & 63;
            int u   = idx & 3;
            const __half* src = g_vth + (size_t)(bh * HS + r) * T + nc * 128 + sc * 32 + u * 8;
            cp16(smb + FB_VB + sc * 5120 + r * 80 + u * 16, src);
        }
        CP_COMMIT;
        CP_WAIT0;
        __syncthreads();

        float acc[2][4][4];
        #pragma unroll
        for (int i = 0; i < 2; i++)
            #pragma unroll
            for (int j = 0; j < 4; j++)
                #pragma unroll
                for (int r = 0; r < 4; r++) acc[i][j][r] = 0.f;

        #pragma unroll
        for (int kc = 0; kc < 2; ++kc) {
            #pragma unroll
            for (int ks = 0; ks < 2; ++ks) {
                uint32_t ahr[2][4], alr[2][4], bhr[2][4], blr[2][4];
                #pragma unroll
                for (int i = 0; i < 2; ++i) {
                    ldsm4(ahr[i], smb + a_off + kc * 5120 + i * (16*80) + ks * 32);
                    ldsm4(alr[i], smb + a_off + 10240 + kc * 5120 + i * (16*80) + ks * 32);
                }
                #pragma unroll
                for (int j = 0; j < 2; ++j) {
                    ldsm4(bhr[j], smb + b_off + kc * 10240 + j * (16*80) + ks * 32);
                    ldsm4(blr[j], smb + b_off + 20480 + kc * 10240 + j * (16*80) + ks * 32);
                }
                #pragma unroll
                for (int i = 0; i < 2; ++i)
                    #pragma unroll
                    for (int j = 0; j < 4; ++j) {
                        uint32_t bfh[2] = { bhr[j >> 1][(j & 1) * 2], bhr[j >> 1][(j & 1) * 2 + 1] };
                        uint32_t bfl[2] = { blr[j >> 1][(j & 1) * 2], blr[j >> 1][(j & 1) * 2 + 1] };
                        mma_f16(acc[i][j], ahr[i], bfh);
                        mma_f16(acc[i][j], ahr[i], bfl);
                        mma_f16(acc[i][j], alr[i], bfh);
                    }
            }
        }

        const __half* Rb = g_rel + ((size_t)bh * T + t0) * T;
        #pragma unroll
        for (int i = 0; i < 2; ++i)
            #pragma unroll
            for (int j = 0; j < 4; ++j)
                #pragma unroll
                for (int rr = 0; rr < 2; ++rr) {
                    const int row = qrow0 + i * 16 + rr * 8;
                    const int col = nc * 128 + warpN * 32 + j * 8 + (lane & 3) * 2;
                    __half2 rv = *(const __half2*)(Rb + (size_t)row * T + col);
                    acc[i][j][rr*2+0] += __half2float(rv.x);
                    acc[i][j][rr*2+1] += __half2float(rv.y);
                }

        float lm[2][2];
        #pragma unroll
        for (int i = 0; i < 2; ++i)
            #pragma unroll
            for (int rr = 0; rr < 2; ++rr) {
                float m = -1e30f;
                #pragma unroll
                for (int j = 0; j < 4; ++j)
                    m = fmaxf(m, fmaxf(acc[i][j][rr*2], acc[i][j][rr*2+1]));
                lm[i][rr] = m;
            }
        #pragma unroll
        for (int o = 1; o <= 2; o <<= 1) {
            #pragma unroll
            for (int i = 0; i < 2; ++i)
                #pragma unroll
                for (int rr = 0; rr < 2; ++rr)
                    lm[i][rr] = fmaxf(lm[i][rr], __shfl_xor_sync(0xffffffffu, lm[i][rr], o));
        }
        if ((lane & 3) == 0) {
            #pragma unroll
            for (int i = 0; i < 2; ++i)
                #pragma unroll
                for (int rr = 0; rr < 2; ++rr)
                    wred[warpN * 64 + qrow0 + i * 16 + rr * 8] = lm[i][rr];
        }
        __syncthreads();
        if (tid < 64) {
            float cm = fmaxf(fmaxf(wred[tid], wred[64 + tid]),
                             fmaxf(wred[128 + tid], wred[192 + tid]));
            float mo = row_m[tid];
            float mn = fmaxf(mo, cm);
            row_f[tid] = __expf(mo - mn);
            row_m[tid] = mn;
        }
        __syncthreads();

        float lsum[2][2];
        #pragma unroll
        for (int i = 0; i < 2; ++i)
            #pragma unroll
            for (int rr = 0; rr < 2; ++rr) {
                const int row = qrow0 + i * 16 + rr * 8;
                const float mn = row_m[row];
                float s = 0.f;
                #pragma unroll
                for (int j = 0; j < 4; ++j) {
                    float p0 = __expf(acc[i][j][rr*2+0] - mn);
                    float p1 = __expf(acc[i][j][rr*2+1] - mn);
                    s += p0 + p1;
                    *(__half2*)(sm + FB_PB + warpN * 5120 + row * 80
                                + (j * 8 + (lane & 3) * 2) * 2) =
                        __halves2half2(__float2half_rn(p0), __float2half_rn(p1));
                }
                lsum[i][rr] = s;
            }
        #pragma unroll
        for (int o = 1; o <= 2; o <<= 1) {
            #pragma unroll
            for (int i = 0; i < 2; ++i)
                #pragma unroll
                for (int rr = 0; rr < 2; ++rr)
                    lsum[i][rr] += __shfl_xor_sync(0xffffffffu, lsum[i][rr], o);
        }
        __syncthreads();
        if ((lane & 3) == 0) {
            #pragma unroll
            for (int i = 0; i < 2; ++i)
                #pragma unroll
                for (int rr = 0; rr < 2; ++rr)
                    wred[warpN * 64 + qrow0 + i * 16 + rr * 8] = lsum[i][rr];
        }
        __syncthreads();
        if (tid < 64) {
            float cs = wred[tid] + wred[64 + tid] + wred[128 + tid] + wred[192 + tid];
            row_l[tid] = row_l[tid] * row_f[tid] + cs;
        }

        #pragma unroll
        for (int i = 0; i < 2; ++i)
            #pragma unroll
            for (int rr = 0; rr < 2; ++rr) {
                const float f = row_f[qrow0 + i * 16 + rr * 8];
                #pragma unroll
                for (int j = 0; j < 2; ++j) {
                    oac[i][j][rr*2+0] *= f;
                    oac[i][j][rr*2+1] *= f;
                }
            }
        #pragma unroll
        for (int c2 = 0; c2 < 4; ++c2) {
            #pragma unroll
            for (int ks = 0; ks < 2; ++ks) {
                uint32_t ar[2][4], vh4[4];
                #pragma unroll
                for (int i = 0; i < 2; ++i)
                    ldsm4(ar[i], smb + pa_off + c2 * 5120 + i * (16*80) + ks * 32);
                ldsm4(vh4, smb + vb_off + c2 * 5120 + ks * 32);
                #pragma unroll
                for (int i = 0; i < 2; ++i)
                    #pragma unroll
                    for (int j = 0; j < 2; ++j) {
                        uint32_t bfh[2] = { vh4[j * 2], vh4[j * 2 + 1] };
                        mma_f16(oac[i][j], ar[i], bfh);
                    }
            }
        }
    }

    __syncthreads();
    #pragma unroll
    for (int i = 0; i < 2; ++i)
        #pragma unroll
        for (int rr = 0; rr < 2; ++rr) {
            const int m = t0 + qrow0 + i * 16 + rr * 8;
            const float inv = 1.f / row_l[qrow0 + i * 16 + rr * 8];
            #pragma unroll
            for (int j = 0; j < 2; ++j) {
                const int cc = warpN * 16 + j * 8 + (lane & 3) * 2;
                *(__half2*)(g_att + (size_t)(b * T + m) * D + h * HS + cc) =
                    __halves2half2(__float2half_rn(oac[i][j][rr*2+0] * inv),
                                   __float2half_rn(oac[i][j][rr*2+1] * inv));
            }
        }
}

// ===================== launch ==============================================
extern "C" void kernel_launch(void* const* d_in, const int* in_sizes, int n_in,
                              void* d_out, int out_size)
{
    (void)in_sizes; (void)n_in; (void)out_size;
    const float* src    = (const float*)d_in[0];
    const float* norm_w = (const float*)d_in[1];
    const float* Wq     = (const float*)d_in[2];
    const float* bq     = (const float*)d_in[3];
    const float* Wk     = (const float*)d_in[4];
    const float* bk     = (const float*)d_in[5];
    const float* Wv     = (const float*)d_in[6];
    const float* bv     = (const float*)d_in[7];
    const float* relp   = (const float*)d_in[8];
    const float* proj_w = (const float*)d_in[9];
    const float* proj_b = (const float*)d_in[10];
    const float* ff_w1  = (const float*)d_in[11];
    const float* ff_b1  = (const float*)d_in[12];
    const float* ff_w2  = (const float*)d_in[13];
    const float* ff_b2  = (const float*)d_in[14];
    float* out = (float*)d_out;

    float *px, *psrc2, *py;
    __half *pxh, *pyh, *pvth, *patt, *phid;
    __half *ppwh, *pf1h, *pf2h, *pw3h;
    cudaGetSymbolAddress((void**)&px,    g_x);
    cudaGetSymbolAddress((void**)&psrc2, g_src2);
    cudaGetSymbolAddress((void**)&py,    g_y);
    cudaGetSymbolAddress((void**)&pxh,   g_xh);
    cudaGetSymbolAddress((void**)&pyh,   g_yh);
    cudaGetSymbolAddress((void**)&pvth,  g_vth);
    cudaGetSymbolAddress((void**)&patt,  g_att);
    cudaGetSymbolAddress((void**)&phid,  g_hid);
    cudaGetSymbolAddress((void**)&pw3h,  g_w3h);
    cudaGetSymbolAddress((void**)&ppwh,  g_pwh);
    cudaGetSymbolAddress((void**)&pf1h,  g_f1h);
    cudaGetSymbolAddress((void**)&pf2h,  g_f2h);

    cudaFuncSetAttribute(gemm_qk, cudaFuncAttributeMaxDynamicSharedMemorySize, G3_SMEM);
    cudaFuncSetAttribute(gemm1<false,false,false,false,true>,  cudaFuncAttributeMaxDynamicSharedMemorySize, G1_SMEM);
    cudaFuncSetAttribute(gemm1<true, false,true, false,false>, cudaFuncAttributeMaxDynamicSharedMemorySize, G1_SMEM);
    cudaFuncSetAttribute(gemm1<false,true, false,true, false>, cudaFuncAttributeMaxDynamicSharedMemorySize, G1_SMEM);
    cudaFuncSetAttribute(mega1, cudaFuncAttributeMaxDynamicSharedMemorySize, REL_SMEM);
    cudaFuncSetAttribute(fused_attn, cudaFuncAttributeMaxDynamicSharedMemorySize, FB_SMEM);

    // 1. qkv weight transpose (768) + rmsnorm(x) (2048 CTAs x 2 rows) fused
    mega0<<<768 + 2048, 256>>>(Wq, Wk, Wv, src, norm_w);

    // 2. q (fp32 + hi/lo) and k8 (hi/lo) in one launch (3-product, 2 CTAs/SM)
    gemm_qk<<<dim3(D/128, BT/128, 2), 256, G3_SMEM>>>(bq, bk);

    // 3. v: transposed single fp16 (1-product)
    gemm1<false,false,false,false,true><<<dim3(D/128, BT/128), 256, G1_SMEM>>>(
        pxh, pw3h + 2*D*D, bv, nullptr, nullptr, pvth, BT, D, D);

    // 4. rel (DRAM umbrella) + proj/ff weight transposes, overlapped
    mega1<<<4096 + 2304, 256, REL_SMEM>>>(relp, proj_w, ff_w1, ff_w2);

    // 5. flash attention (scores + rel + online softmax + AV)
    fused_attn<<<dim3(T/64, BATCH*H), 256, FB_SMEM>>>();

    // 6. src2 = x + att @ proj_w + proj_b
    gemm1<true,false,true,false,false><<<dim3(D/128, BT/128), 256, G1_SMEM>>>(
        patt, ppwh, proj_b, px, psrc2, nullptr, BT, D, D);

    // 7. y = rmsnorm(src2)
    rmsnorm_kernel<<<BT, 128>>>(psrc2, norm_w, py, pyh);

    // 8. h = gelu(y @ ff_w1 + ff_b1)
    gemm1<false,true,false,true,false><<<dim3(FF/128, BT/128), 256, G1_SMEM>>>(
        pyh, pf1h, ff_b1, nullptr, nullptr, phid, BT, FF, D);

    // 9. out = y + h @ ff_w2 + ff_b2
    gemm1<true,false,true,false,false><<<dim3(D/128, BT/128), 256, G1_SMEM>>>(
        phid, pf2h, ff_b2, py, out, nullptr, BT, D, FF);
}